// round 5
// baseline (speedup 1.0000x reference)
#include <cuda_runtime.h>
#include <cuda_bf16.h>
#include <math.h>

// ---------------- problem constants ----------------
#define BATCH 2
#define CCH   512
#define NPIX  1024     // 32*32
#define GR    8
#define CG    64
#define NBG   16       // BATCH*GR
#define KVP   64       // 8*8
#define DIMH  64
#define SCALE 0.125f
#define EPSBN 1e-5f

// ---------------- device scratch (no allocation allowed) ----------------
__device__ float g_s1[CCH], g_t1[CCH], g_s2[CCH], g_t2[CCH];
__device__ float g_x1[BATCH*CCH*NPIX];      // bn1(x)
__device__ float g_q [BATCH*CCH*NPIX];      // grouped conv q (unscaled)
__device__ float g_vgrid[NBG*KVP*2];        // normalized sample grid (vx,vy)
__device__ float g_kv[NBG*CG*KVP];          // sampled features
__device__ float g_k [NBG*CG*KVP];
__device__ float g_v [NBG*CG*KVP];
__device__ float g_bias[NBG*NPIX*KVP];      // CPB bias
__device__ float g_attn[BATCH*CCH*NPIX];    // attention output (head-major = channel-major)
__device__ float g_x2[BATCH*CCH*NPIX];      // x + out-proj
__device__ float g_h [BATCH*4*CCH*NPIX];    // FFN hidden

// ---------------- batchnorm stats ----------------
__global__ void bn_stats(const float* __restrict__ x, const float* __restrict__ g,
                         const float* __restrict__ b, float* __restrict__ s, float* __restrict__ t) {
    int c = blockIdx.x;
    float sum = 0.f, sq = 0.f;
    for (int e = threadIdx.x; e < BATCH*NPIX; e += 256) {
        int bb = e >> 10, p = e & 1023;
        float v = x[(bb*CCH + c)*NPIX + p];
        sum += v; sq += v*v;
    }
    __shared__ float rs[256], rq[256];
    rs[threadIdx.x] = sum; rq[threadIdx.x] = sq;
    __syncthreads();
    for (int st = 128; st > 0; st >>= 1) {
        if (threadIdx.x < st) { rs[threadIdx.x] += rs[threadIdx.x+st]; rq[threadIdx.x] += rq[threadIdx.x+st]; }
        __syncthreads();
    }
    if (threadIdx.x == 0) {
        float m   = rs[0] / (float)(BATCH*NPIX);
        float var = rq[0] / (float)(BATCH*NPIX) - m*m;
        float sc  = g[c] * rsqrtf(var + EPSBN);
        s[c] = sc;
        t[c] = b[c] - m*sc;
    }
}

__global__ void bn_apply(const float* __restrict__ x, const float* __restrict__ s,
                         const float* __restrict__ t, float* __restrict__ y) {
    int i = blockIdx.x*256 + threadIdx.x;
    int c = (i >> 10) & (CCH-1);
    y[i] = x[i]*s[c] + t[c];
}

// ---------------- grouped 1x1 conv:  out[bg,o,p] = sum_ci w[g,o,ci] * in[bg,ci,p] ----------------
__global__ void gconv(const float* __restrict__ in, const float* __restrict__ w,
                      float* __restrict__ out, int npix) {
    int bg = blockIdx.x;
    int g  = bg & (GR-1);
    int pix = blockIdx.y*blockDim.x + threadIdx.x;
    __shared__ float ws[CG*CG];
    for (int e = threadIdx.x; e < CG*CG; e += blockDim.x) ws[e] = w[g*CG*CG + e];
    __syncthreads();
    if (pix >= npix) return;
    float xr[CG];
    #pragma unroll
    for (int ci = 0; ci < CG; ci++) xr[ci] = in[(bg*CG + ci)*npix + pix];
    #pragma unroll 4
    for (int o = 0; o < CG; o++) {
        float acc = 0.f;
        #pragma unroll
        for (int ci = 0; ci < CG; ci++) acc += ws[o*CG + ci] * xr[ci];
        out[(bg*CG + o)*npix + pix] = acc;
    }
}

// ---------------- offsets: dwconv6x6 s4 p1 + gelu + pointwise + tanh -> normalized grid ----------------
__global__ void offsets_kernel(const float* __restrict__ q, const float* __restrict__ dww,
                               const float* __restrict__ dwb, const float* __restrict__ pww,
                               float* __restrict__ vgrid) {
    int bg = blockIdx.x;
    int tid = threadIdx.x;               // 64 threads, one per 8x8 output pos
    int oy = tid >> 3, ox = tid & 7;
    float acc0 = 0.f, acc1 = 0.f;
    for (int c = 0; c < CG; c++) {
        const float* wc = dww + c*36;
        const float* qc = q + (bg*CG + c)*NPIX;
        float s = 0.f;
        #pragma unroll
        for (int ky = 0; ky < 6; ky++) {
            int iy = oy*4 - 1 + ky;
            if (iy < 0 || iy >= 32) continue;
            #pragma unroll
            for (int kx = 0; kx < 6; kx++) {
                int ix = ox*4 - 1 + kx;
                if (ix < 0 || ix >= 32) continue;
                s += wc[ky*6 + kx] * qc[iy*32 + ix];
            }
        }
        s += dwb[c];
        float ge = 0.5f*s*(1.f + erff(s*0.70710678118654752f));  // exact gelu
        acc0 += pww[c]      * ge;
        acc1 += pww[CG + c] * ge;
    }
    float offx = tanhf(acc0)*4.f;
    float offy = tanhf(acc1)*4.f;
    float vx = 2.f*((float)ox + offx)/7.f - 1.f;
    float vy = 2.f*((float)oy + offy)/7.f - 1.f;
    vgrid[bg*(KVP*2) + tid*2 + 0] = vx;
    vgrid[bg*(KVP*2) + tid*2 + 1] = vy;
}

// ---------------- bilinear grid sample (zero padding) ----------------
__global__ void gridsample_kernel(const float* __restrict__ x1, const float* __restrict__ vgrid,
                                  float* __restrict__ kv) {
    int bg = blockIdx.x;
    for (int e = threadIdx.x; e < CG*KVP; e += blockDim.x) {
        int c = e >> 6, pos = e & 63;
        float vx = vgrid[bg*(KVP*2) + pos*2 + 0];
        float vy = vgrid[bg*(KVP*2) + pos*2 + 1];
        float xf = ((vx + 1.f)*32.f - 1.f)*0.5f;
        float yf = ((vy + 1.f)*32.f - 1.f)*0.5f;
        float x0 = floorf(xf), y0 = floorf(yf);
        float wx = xf - x0, wy = yf - y0;
        int x0i = (int)x0, y0i = (int)y0;
        const float* img = x1 + (bg*CG + c)*NPIX;
        float v00 = 0.f, v10 = 0.f, v01 = 0.f, v11 = 0.f;
        bool xa = (x0i   >= 0 && x0i   < 32), xb = (x0i+1 >= 0 && x0i+1 < 32);
        bool ya = (y0i   >= 0 && y0i   < 32), yb = (y0i+1 >= 0 && y0i+1 < 32);
        if (xa && ya) v00 = img[y0i*32 + x0i];
        if (xb && ya) v10 = img[y0i*32 + x0i+1];
        if (xa && yb) v01 = img[(y0i+1)*32 + x0i];
        if (xb && yb) v11 = img[(y0i+1)*32 + x0i+1];
        float v = v00*(1.f-wx)*(1.f-wy) + v10*wx*(1.f-wy) + v01*(1.f-wx)*wy + v11*wx*wy;
        kv[(bg*CG + c)*KVP + pos] = v;
    }
}

// ---------------- CPB bias MLP (fused 2->128 relu, 128x128 GEMM relu, 128->1) ----------------
// block = (bg, 2 queries) -> 128 points. smem: w1 (128x128), h1 (128x129), red (128x17)
#define BIAS_SMEM_FLOATS (128*128 + 128*129 + 128*17 + 256 + 128 + 128 + 128)
__global__ void bias_kernel(const float* __restrict__ vgrid,
                            const float* __restrict__ w0, const float* __restrict__ b0,
                            const float* __restrict__ w1, const float* __restrict__ b1,
                            const float* __restrict__ w2, const float* __restrict__ b2,
                            float* __restrict__ bias_out) {
    extern __shared__ float sm[];
    float* w1s = sm;                   // 16384
    float* h1s = w1s + 128*128;        // 128*129 (padded)
    float* red = h1s + 128*129;        // 128*17
    float* w0s = red + 128*17;         // 256
    float* b0s = w0s + 256;            // 128
    float* b1s = b0s + 128;            // 128
    float* w2s = b1s + 128;            // 128
    int tid = threadIdx.x;
    int bg  = blockIdx.x >> 9;
    int i0  = (blockIdx.x & 511) << 1;

    for (int e = tid; e < 128*128; e += 256) w1s[e] = w1[e];
    if (tid < 256) { w0s[tid] = w0[tid]; }
    if (tid < 128) { b0s[tid] = b0[tid]; b1s[tid] = b1[tid]; w2s[tid] = w2[tid]; }

    // features + layer0 (two threads per point, 64 k's each)
    {
        int p = tid >> 1;
        int half = (tid & 1) * 64;
        int i = i0 + (p >> 6), j = p & 63;
        float qx = 2.f*(float)(i & 31)/31.f - 1.f;
        float qy = 2.f*(float)(i >> 5)/31.f - 1.f;
        float px = qx - vgrid[bg*(KVP*2) + j*2 + 0];
        float py = qy - vgrid[bg*(KVP*2) + j*2 + 1];
        float f0 = copysignf(log1pf(fabsf(px)), px);
        float f1 = copysignf(log1pf(fabsf(py)), py);
        __syncthreads();   // w0s/b0s ready
        #pragma unroll 8
        for (int k = half; k < half + 64; k++) {
            float h = f0*w0s[k] + f1*w0s[128 + k] + b0s[k];
            h1s[p*129 + k] = h > 0.f ? h : 0.f;
        }
    }
    __syncthreads();

    // 128x128x128 GEMM, 8x8 register tiles
    int ty = tid >> 4, tx = tid & 15;
    int p0 = ty*8, k0 = tx*8;
    float acc[8][8];
    #pragma unroll
    for (int r = 0; r < 8; r++)
        #pragma unroll
        for (int c = 0; c < 8; c++) acc[r][c] = 0.f;

    #pragma unroll 4
    for (int kin = 0; kin < 128; kin++) {
        float a[8], bfr[8];
        #pragma unroll
        for (int r = 0; r < 8; r++) a[r] = h1s[(p0 + r)*129 + kin];
        #pragma unroll
        for (int c = 0; c < 8; c++) bfr[c] = w1s[kin*128 + k0 + c];
        #pragma unroll
        for (int r = 0; r < 8; r++)
            #pragma unroll
            for (int c = 0; c < 8; c++) acc[r][c] += a[r]*bfr[c];
    }

    // epilogue: relu + dot with w2, partial reduce over tx
    #pragma unroll
    for (int r = 0; r < 8; r++) {
        float part = 0.f;
        #pragma unroll
        for (int c = 0; c < 8; c++) {
            float h = acc[r][c] + b1s[k0 + c];
            part += (h > 0.f ? h : 0.f) * w2s[k0 + c];
        }
        red[(p0 + r)*17 + tx] = part;
    }
    __syncthreads();
    if (tid < 128) {
        float s = b2[0];
        #pragma unroll
        for (int u = 0; u < 16; u++) s += red[tid*17 + u];
        int i = i0 + (tid >> 6), j = tid & 63;
        bias_out[((bg << 10) + i)*KVP + j] = s;
    }
}

// ---------------- attention: sim + bias, softmax over 64 kv, @V ----------------
#define ATT_QT 128
#define ATT_SMEM_FLOATS (64*64 + 64*64 + ATT_QT*65)
__global__ void attn_kernel(const float* __restrict__ q, const float* __restrict__ karr,
                            const float* __restrict__ varr, const float* __restrict__ bias,
                            float* __restrict__ outp) {
    extern __shared__ float sm[];
    float* ks = sm;                 // [j][d]
    float* vs = sm + 64*64;         // [j][d]
    float* ss = sm + 2*64*64;       // [tid][65]
    int bg = blockIdx.x;
    int i  = blockIdx.y*ATT_QT + threadIdx.x;
    for (int e = threadIdx.x; e < CG*KVP; e += ATT_QT) {
        int d = e >> 6, j = e & 63;
        ks[j*64 + d] = karr[(bg*CG + d)*KVP + j];
        vs[j*64 + d] = varr[(bg*CG + d)*KVP + j];
    }
    __syncthreads();
    float qr[DIMH];
    #pragma unroll
    for (int d = 0; d < DIMH; d++) qr[d] = q[(bg*CG + d)*NPIX + i] * SCALE;
    const float* brow = bias + (bg*NPIX + i)*KVP;
    float m = -1e30f;
    for (int j = 0; j < KVP; j++) {
        float s = 0.f;
        #pragma unroll
        for (int d = 0; d < DIMH; d++) s += qr[d]*ks[j*64 + d];
        s += brow[j];
        ss[threadIdx.x*65 + j] = s;
        m = fmaxf(m, s);
    }
    float l = 0.f;
    float o[DIMH];
    #pragma unroll
    for (int d = 0; d < DIMH; d++) o[d] = 0.f;
    for (int j = 0; j < KVP; j++) {
        float p = expf(ss[threadIdx.x*65 + j] - m);
        l += p;
        #pragma unroll
        for (int d = 0; d < DIMH; d++) o[d] += p*vs[j*64 + d];
    }
    float inv = 1.f / l;
    #pragma unroll
    for (int d = 0; d < DIMH; d++) outp[(bg*CG + d)*NPIX + i] = o[d]*inv;
}

// ---------------- generic tiled SGEMM: C = act(A[M,K] @ (B*s+t)[K,N] + bias[M]) (+resid) ----------------
__global__ void sgemm_kernel(const float* __restrict__ A, const float* __restrict__ B,
                             const float* __restrict__ bias, const float* __restrict__ scaleB,
                             const float* __restrict__ shiftB, const float* __restrict__ resid,
                             float* __restrict__ C, int M, int N, int K, int act) {
    __shared__ float As[16][128];
    __shared__ float Bs[16][132];
    int tid = threadIdx.x;
    int n0 = blockIdx.x*128, m0 = blockIdx.y*128;
    int zB = blockIdx.z * K * N;
    int zC = blockIdx.z * M * N;
    int ty = tid >> 4, tx = tid & 15;
    int aRow = tid >> 1, aCol = (tid & 1)*8;
    int bRow = tid >> 4, bCol = (tid & 15)*8;
    float acc[8][8];
    #pragma unroll
    for (int r = 0; r < 8; r++)
        #pragma unroll
        for (int c = 0; c < 8; c++) acc[r][c] = 0.f;

    for (int k0 = 0; k0 < K; k0 += 16) {
        #pragma unroll
        for (int c2 = 0; c2 < 8; c2++)
            As[aCol + c2][aRow] = A[(m0 + aRow)*K + k0 + aCol + c2];
        float sc = scaleB ? scaleB[k0 + bRow] : 1.f;
        float sh = scaleB ? shiftB[k0 + bRow] : 0.f;
        const float* brp = B + zB + (k0 + bRow)*N + n0 + bCol;
        #pragma unroll
        for (int c2 = 0; c2 < 8; c2++)
            Bs[bRow][bCol + c2] = brp[c2]*sc + sh;
        __syncthreads();
        #pragma unroll
        for (int kk = 0; kk < 16; kk++) {
            float a[8], bfr[8];
            #pragma unroll
            for (int r = 0; r < 8; r++) a[r] = As[kk][ty*8 + r];
            #pragma unroll
            for (int c2 = 0; c2 < 8; c2++) bfr[c2] = Bs[kk][tx*8 + c2];
            #pragma unroll
            for (int r = 0; r < 8; r++)
                #pragma unroll
                for (int c2 = 0; c2 < 8; c2++) acc[r][c2] += a[r]*bfr[c2];
        }
        __syncthreads();
    }
    #pragma unroll
    for (int r = 0; r < 8; r++) {
        int m = m0 + ty*8 + r;
        float bm = bias[m];
        #pragma unroll
        for (int c2 = 0; c2 < 8; c2++) {
            int n = n0 + tx*8 + c2;
            float v = acc[r][c2] + bm;
            if (act == 1) v = 0.5f*v*(1.f + erff(v*0.70710678118654752f));
            if (resid) v += resid[zC + m*N + n];
            C[zC + m*N + n] = v;
        }
    }
}

// ---------------- launch ----------------
extern "C" void kernel_launch(void* const* d_in, const int* in_sizes, int n_in,
                              void* d_out, int out_size) {
    const float* x        = (const float*)d_in[0];
    const float* n1_g     = (const float*)d_in[1];
    const float* n1_b     = (const float*)d_in[2];
    const float* n2_g     = (const float*)d_in[3];
    const float* n2_b     = (const float*)d_in[4];
    const float* q_w      = (const float*)d_in[5];
    const float* k_w      = (const float*)d_in[6];
    const float* v_w      = (const float*)d_in[7];
    const float* off_dw_w = (const float*)d_in[8];
    const float* off_dw_b = (const float*)d_in[9];
    const float* off_pw_w = (const float*)d_in[10];
    const float* cpb_w0   = (const float*)d_in[11];
    const float* cpb_b0   = (const float*)d_in[12];
    const float* cpb_w1   = (const float*)d_in[13];
    const float* cpb_b1   = (const float*)d_in[14];
    const float* cpb_w2   = (const float*)d_in[15];
    const float* cpb_b2   = (const float*)d_in[16];
    const float* out_w    = (const float*)d_in[17];
    const float* out_b    = (const float*)d_in[18];
    const float* mlp_w1   = (const float*)d_in[19];
    const float* mlp_b1   = (const float*)d_in[20];
    const float* mlp_w2   = (const float*)d_in[21];
    const float* mlp_b2   = (const float*)d_in[22];
    float* out = (float*)d_out;

    float *p_s1, *p_t1, *p_s2, *p_t2, *p_x1, *p_q, *p_vg, *p_kv, *p_k, *p_v, *p_bias, *p_attn, *p_x2, *p_h;
    cudaGetSymbolAddress((void**)&p_s1, g_s1);
    cudaGetSymbolAddress((void**)&p_t1, g_t1);
    cudaGetSymbolAddress((void**)&p_s2, g_s2);
    cudaGetSymbolAddress((void**)&p_t2, g_t2);
    cudaGetSymbolAddress((void**)&p_x1, g_x1);
    cudaGetSymbolAddress((void**)&p_q,  g_q);
    cudaGetSymbolAddress((void**)&p_vg, g_vgrid);
    cudaGetSymbolAddress((void**)&p_kv, g_kv);
    cudaGetSymbolAddress((void**)&p_k,  g_k);
    cudaGetSymbolAddress((void**)&p_v,  g_v);
    cudaGetSymbolAddress((void**)&p_bias, g_bias);
    cudaGetSymbolAddress((void**)&p_attn, g_attn);
    cudaGetSymbolAddress((void**)&p_x2, g_x2);
    cudaGetSymbolAddress((void**)&p_h,  g_h);

    cudaFuncSetAttribute(bias_kernel, cudaFuncAttributeMaxDynamicSharedMemorySize,
                         BIAS_SMEM_FLOATS*4);
    cudaFuncSetAttribute(attn_kernel, cudaFuncAttributeMaxDynamicSharedMemorySize,
                         ATT_SMEM_FLOATS*4);

    // 1) bn1
    bn_stats<<<CCH, 256>>>(x, n1_g, n1_b, p_s1, p_t1);
    bn_apply<<<BATCH*CCH*NPIX/256, 256>>>(x, p_s1, p_t1, p_x1);
    // 2) q = grouped conv
    gconv<<<dim3(NBG, 4), 256>>>(p_x1, q_w, p_q, NPIX);
    // 3) offsets -> normalized sample grid
    offsets_kernel<<<NBG, 64>>>(p_q, off_dw_w, off_dw_b, off_pw_w, p_vg);
    // 4) bilinear sample
    gridsample_kernel<<<NBG, 256>>>(p_x1, p_vg, p_kv);
    // 5) k, v grouped convs
    gconv<<<dim3(NBG, 1), 64>>>(p_kv, k_w, p_k, KVP);
    gconv<<<dim3(NBG, 1), 64>>>(p_kv, v_w, p_v, KVP);
    // 6) CPB bias MLP
    bias_kernel<<<NBG*512, 256, BIAS_SMEM_FLOATS*4>>>(p_vg, cpb_w0, cpb_b0, cpb_w1, cpb_b1,
                                                      cpb_w2, cpb_b2, p_bias);
    // 7) attention
    attn_kernel<<<dim3(NBG, NPIX/ATT_QT), ATT_QT, ATT_SMEM_FLOATS*4>>>(p_q, p_k, p_v, p_bias, p_attn);
    // 8) out projection + residual (x2 = x + W_out @ attn + b)
    sgemm_kernel<<<dim3(8, 4, BATCH), 256>>>(out_w, p_attn, out_b, nullptr, nullptr, x, p_x2,
                                             512, 1024, 512, 0);
    // 9) bn2 + FFN
    bn_stats<<<CCH, 256>>>(p_x2, n2_g, n2_b, p_s2, p_t2);
    sgemm_kernel<<<dim3(8, 16, BATCH), 256>>>(mlp_w1, p_x2, mlp_b1, p_s2, p_t2, nullptr, p_h,
                                              2048, 1024, 512, 1);
    sgemm_kernel<<<dim3(8, 4, BATCH), 256>>>(mlp_w2, p_h, mlp_b2, nullptr, nullptr, p_x2, out,
                                             512, 1024, 2048, 0);
}

// round 8
// speedup vs baseline: 1.1248x; 1.1248x over previous
#include <cuda_runtime.h>
#include <cuda_bf16.h>
#include <math.h>

// ---------------- problem constants ----------------
#define BATCH 2
#define CCH   512
#define NPIX  1024     // 32*32
#define GR    8
#define CG    64
#define NBG   16       // BATCH*GR
#define KVP   64       // 8*8
#define DIMH  64
#define SCALE 0.125f
#define EPSBN 1e-5f

typedef unsigned long long u64;

// ---------------- f32x2 packed helpers ----------------
__device__ __forceinline__ u64 pack2(float lo, float hi) {
    u64 r; asm("mov.b64 %0, {%1,%2};" : "=l"(r) : "f"(lo), "f"(hi)); return r;
}
__device__ __forceinline__ void unpack2(u64 v, float& lo, float& hi) {
    asm("mov.b64 {%0,%1}, %2;" : "=f"(lo), "=f"(hi) : "l"(v));
}
__device__ __forceinline__ void ffma2(u64& d, u64 a, u64 b) {
    asm("fma.rn.f32x2 %0, %1, %2, %0;" : "+l"(d) : "l"(a), "l"(b));
}
__device__ __forceinline__ u64 lds64(const float* p) {
    return *reinterpret_cast<const u64*>(p);
}

// ---------------- device scratch (no allocation allowed) ----------------
__device__ float g_s1[CCH], g_t1[CCH], g_s2[CCH], g_t2[CCH];
__device__ float g_x1[BATCH*CCH*NPIX];      // bn1(x)
__device__ float g_q [BATCH*CCH*NPIX];      // grouped conv q (unscaled)
__device__ float g_offpart[NBG*16*KVP*2];   // offset partials
__device__ float g_vgrid[NBG*KVP*2];        // normalized sample grid (vx,vy)
__device__ float g_kv[NBG*CG*KVP];          // sampled features
__device__ float g_k [NBG*CG*KVP];
__device__ float g_v [NBG*CG*KVP];
__device__ float g_bias[NBG*NPIX*KVP];      // CPB bias
__device__ float g_attn[BATCH*CCH*NPIX];    // attention output
__device__ float g_x2[BATCH*CCH*NPIX];      // x + out-proj
__device__ float g_h [BATCH*4*CCH*NPIX];    // FFN hidden

// ---------------- batchnorm stats ----------------
__global__ void bn_stats(const float* __restrict__ x, const float* __restrict__ g,
                         const float* __restrict__ b, float* __restrict__ s, float* __restrict__ t) {
    int c = blockIdx.x;
    float sum = 0.f, sq = 0.f;
    for (int e = threadIdx.x; e < BATCH*NPIX; e += 256) {
        int bb = e >> 10, p = e & 1023;
        float v = x[(bb*CCH + c)*NPIX + p];
        sum += v; sq += v*v;
    }
    __shared__ float rs[256], rq[256];
    rs[threadIdx.x] = sum; rq[threadIdx.x] = sq;
    __syncthreads();
    for (int st = 128; st > 0; st >>= 1) {
        if (threadIdx.x < st) { rs[threadIdx.x] += rs[threadIdx.x+st]; rq[threadIdx.x] += rq[threadIdx.x+st]; }
        __syncthreads();
    }
    if (threadIdx.x == 0) {
        float m   = rs[0] / (float)(BATCH*NPIX);
        float var = rq[0] / (float)(BATCH*NPIX) - m*m;
        float sc  = g[c] * rsqrtf(var + EPSBN);
        s[c] = sc;
        t[c] = b[c] - m*sc;
    }
}

__global__ void bn_apply(const float* __restrict__ x, const float* __restrict__ s,
                         const float* __restrict__ t, float* __restrict__ y) {
    int i = blockIdx.x*256 + threadIdx.x;
    int c = (i >> 10) & (CCH-1);
    y[i] = x[i]*s[c] + t[c];
}

// ---------------- grouped 1x1 conv ----------------
__global__ void gconv(const float* __restrict__ in, const float* __restrict__ w,
                      float* __restrict__ out, int npix) {
    int bg = blockIdx.x;
    int g  = bg & (GR-1);
    int pix = blockIdx.y*blockDim.x + threadIdx.x;
    __shared__ float ws[CG*CG];
    for (int e = threadIdx.x; e < CG*CG; e += blockDim.x) ws[e] = w[g*CG*CG + e];
    __syncthreads();
    if (pix >= npix) return;
    float xr[CG];
    #pragma unroll
    for (int ci = 0; ci < CG; ci++) xr[ci] = in[(bg*CG + ci)*npix + pix];
    #pragma unroll 4
    for (int o = 0; o < CG; o++) {
        float acc = 0.f;
        #pragma unroll
        for (int ci = 0; ci < CG; ci++) acc += ws[o*CG + ci] * xr[ci];
        out[(bg*CG + o)*npix + pix] = acc;
    }
}

// ---------------- offsets, stage 1: per-channel-group partial sums ----------------
__global__ void offsets_part(const float* __restrict__ q, const float* __restrict__ dww,
                             const float* __restrict__ dwb, const float* __restrict__ pww,
                             float* __restrict__ part) {
    int bg = blockIdx.x, grp = blockIdx.y;
    int tid = threadIdx.x;               // 64 threads, one per 8x8 output pos
    int oy = tid >> 3, ox = tid & 7;
    float acc0 = 0.f, acc1 = 0.f;
    #pragma unroll
    for (int cc = 0; cc < 4; cc++) {
        int c = grp*4 + cc;
        const float* wc = dww + c*36;
        const float* qc = q + (bg*CG + c)*NPIX;
        float s = 0.f;
        #pragma unroll
        for (int ky = 0; ky < 6; ky++) {
            int iy = oy*4 - 1 + ky;
            if (iy < 0 || iy >= 32) continue;
            #pragma unroll
            for (int kx = 0; kx < 6; kx++) {
                int ix = ox*4 - 1 + kx;
                if (ix < 0 || ix >= 32) continue;
                s += wc[ky*6 + kx] * qc[iy*32 + ix];
            }
        }
        s += dwb[c];
        float ge = 0.5f*s*(1.f + erff(s*0.70710678118654752f));  // exact gelu
        acc0 += pww[c]      * ge;
        acc1 += pww[CG + c] * ge;
    }
    part[((bg*16 + grp)*KVP + tid)*2 + 0] = acc0;
    part[((bg*16 + grp)*KVP + tid)*2 + 1] = acc1;
}

// ---------------- offsets, stage 2: reduce + tanh + grid normalize ----------------
__global__ void offsets_finish(const float* __restrict__ part, float* __restrict__ vgrid) {
    int bg = blockIdx.x;
    int tid = threadIdx.x;               // 64
    int oy = tid >> 3, ox = tid & 7;
    float a0 = 0.f, a1 = 0.f;
    #pragma unroll
    for (int g = 0; g < 16; g++) {
        a0 += part[((bg*16 + g)*KVP + tid)*2 + 0];
        a1 += part[((bg*16 + g)*KVP + tid)*2 + 1];
    }
    float offx = tanhf(a0)*4.f;
    float offy = tanhf(a1)*4.f;
    float vx = 2.f*((float)ox + offx)/7.f - 1.f;
    float vy = 2.f*((float)oy + offy)/7.f - 1.f;
    vgrid[bg*(KVP*2) + tid*2 + 0] = vx;
    vgrid[bg*(KVP*2) + tid*2 + 1] = vy;
}

// ---------------- bilinear grid sample (zero padding) ----------------
__global__ void gridsample_kernel(const float* __restrict__ x1, const float* __restrict__ vgrid,
                                  float* __restrict__ kv) {
    int bg = blockIdx.x;
    for (int e = threadIdx.x; e < CG*KVP; e += blockDim.x) {
        int c = e >> 6, pos = e & 63;
        float vx = vgrid[bg*(KVP*2) + pos*2 + 0];
        float vy = vgrid[bg*(KVP*2) + pos*2 + 1];
        float xf = ((vx + 1.f)*32.f - 1.f)*0.5f;
        float yf = ((vy + 1.f)*32.f - 1.f)*0.5f;
        float x0 = floorf(xf), y0 = floorf(yf);
        float wx = xf - x0, wy = yf - y0;
        int x0i = (int)x0, y0i = (int)y0;
        const float* img = x1 + (bg*CG + c)*NPIX;
        float v00 = 0.f, v10 = 0.f, v01 = 0.f, v11 = 0.f;
        bool xa = (x0i   >= 0 && x0i   < 32), xb = (x0i+1 >= 0 && x0i+1 < 32);
        bool ya = (y0i   >= 0 && y0i   < 32), yb = (y0i+1 >= 0 && y0i+1 < 32);
        if (xa && ya) v00 = img[y0i*32 + x0i];
        if (xb && ya) v10 = img[y0i*32 + x0i+1];
        if (xa && yb) v01 = img[(y0i+1)*32 + x0i];
        if (xb && yb) v11 = img[(y0i+1)*32 + x0i+1];
        float v = v00*(1.f-wx)*(1.f-wy) + v10*wx*(1.f-wy) + v01*(1.f-wx)*wy + v11*wx*wy;
        kv[(bg*CG + c)*KVP + pos] = v;
    }
}

// ---------------- CPB bias MLP: FFMA2 over column pairs, small per-thread tile ----------------
// 512 threads. Each thread: 4 rows (points) x 4 col-pairs (8 cols). acc = u64[4][4] = 32 regs.
// w1s row-major [kin][col]; col pair (32*cp + 2*tx, +1) -> conflict-free LDS.64.
#define BIAS_SMEM_FLOATS (128*128 + 128*129 + 128*17 + 256 + 128 + 128 + 128)
__global__ void __launch_bounds__(512, 1)
bias_kernel(const float* __restrict__ vgrid,
            const float* __restrict__ w0, const float* __restrict__ b0,
            const float* __restrict__ w1, const float* __restrict__ b1,
            const float* __restrict__ w2, const float* __restrict__ b2,
            float* __restrict__ bias_out) {
    extern __shared__ float sm[];
    float* w1s = sm;                   // [kin][col] 128*128
    float* h1s = w1s + 128*128;        // [p][kin]   128*129
    float* red = h1s + 128*129;        // 128*17
    float* w0s = red + 128*17;         // 256
    float* b0s = w0s + 256;            // 128
    float* b1s = b0s + 128;            // 128
    float* w2s = b1s + 128;            // 128
    int tid = threadIdx.x;
    int bg  = blockIdx.x >> 9;
    int i0  = (blockIdx.x & 511) << 1;

    for (int e = tid; e < 128*128; e += 512) w1s[e] = w1[e];
    if (tid < 256) w0s[tid] = w0[tid];
    if (tid < 128) { b0s[tid] = b0[tid]; b1s[tid] = b1[tid]; w2s[tid] = w2[tid]; }

    // features + layer0 (four threads per point, 32 k's each)
    {
        int p = tid >> 2;
        int seg = (tid & 3) * 32;
        int i = i0 + (p >> 6), j = p & 63;
        float qx = 2.f*(float)(i & 31)/31.f - 1.f;
        float qy = 2.f*(float)(i >> 5)/31.f - 1.f;
        float px = qx - vgrid[bg*(KVP*2) + j*2 + 0];
        float py = qy - vgrid[bg*(KVP*2) + j*2 + 1];
        float f0 = copysignf(log1pf(fabsf(px)), px);
        float f1 = copysignf(log1pf(fabsf(py)), py);
        __syncthreads();   // w0s/b0s ready
        #pragma unroll 8
        for (int k = seg; k < seg + 32; k++) {
            float h = f0*w0s[k] + f1*w0s[128 + k] + b0s[k];
            h1s[p*129 + k] = h > 0.f ? h : 0.f;
        }
    }
    __syncthreads();

    // 128x128x128 GEMM: thread (ty,tx): rows p0..p0+3, col pairs 32*cp + 2*tx
    int ty = tid >> 4;         // 0..31
    int tx = tid & 15;         // 0..15
    int p0 = ty*4;
    u64 acc[4][4];
    #pragma unroll
    for (int r = 0; r < 4; r++)
        #pragma unroll
        for (int c = 0; c < 4; c++) acc[r][c] = 0ull;

    #pragma unroll 2
    for (int kin = 0; kin < 128; kin++) {
        u64 ap[4], bp[4];
        #pragma unroll
        for (int r = 0; r < 4; r++) {
            float a = h1s[(p0 + r)*129 + kin];
            ap[r] = pack2(a, a);
        }
        #pragma unroll
        for (int c = 0; c < 4; c++)
            bp[c] = lds64(&w1s[kin*128 + 32*c + 2*tx]);
        #pragma unroll
        for (int r = 0; r < 4; r++)
            #pragma unroll
            for (int c = 0; c < 4; c++) ffma2(acc[r][c], ap[r], bp[c]);
    }

    // epilogue: relu + dot with w2 over owned 8 cols, partial reduce over tx
    #pragma unroll
    for (int r = 0; r < 4; r++) {
        float part = 0.f;
        #pragma unroll
        for (int c = 0; c < 4; c++) {
            int col = 32*c + 2*tx;
            float lo, hi; unpack2(acc[r][c], lo, hi);
            float h0 = lo + b1s[col];
            float h1v = hi + b1s[col + 1];
            part += (h0  > 0.f ? h0  : 0.f) * w2s[col];
            part += (h1v > 0.f ? h1v : 0.f) * w2s[col + 1];
        }
        red[(p0 + r)*17 + tx] = part;
    }
    __syncthreads();
    if (tid < 128) {
        float s = b2[0];
        #pragma unroll
        for (int u = 0; u < 16; u++) s += red[tid*17 + u];
        int i = i0 + (tid >> 6), j = tid & 63;
        bias_out[((bg << 10) + i)*KVP + j] = s;
    }
}

// ---------------- attention: sim + bias, softmax over 64 kv, @V ----------------
#define ATT_QT 128
#define ATT_SMEM_FLOATS (64*64 + 64*64 + ATT_QT*65)
__global__ void attn_kernel(const float* __restrict__ q, const float* __restrict__ karr,
                            const float* __restrict__ varr, const float* __restrict__ bias,
                            float* __restrict__ outp) {
    extern __shared__ float sm[];
    float* ks = sm;                 // [j][d]
    float* vs = sm + 64*64;         // [j][d]
    float* ss = sm + 2*64*64;       // [tid][65]
    int bg = blockIdx.x;
    int i  = blockIdx.y*ATT_QT + threadIdx.x;
    for (int e = threadIdx.x; e < CG*KVP; e += ATT_QT) {
        int d = e >> 6, j = e & 63;
        ks[j*64 + d] = karr[(bg*CG + d)*KVP + j];
        vs[j*64 + d] = varr[(bg*CG + d)*KVP + j];
    }
    __syncthreads();
    float qr[DIMH];
    #pragma unroll
    for (int d = 0; d < DIMH; d++) qr[d] = q[(bg*CG + d)*NPIX + i] * SCALE;
    const float* brow = bias + (bg*NPIX + i)*KVP;
    float m = -1e30f;
    for (int j = 0; j < KVP; j++) {
        float s = 0.f;
        #pragma unroll
        for (int d = 0; d < DIMH; d++) s += qr[d]*ks[j*64 + d];
        s += brow[j];
        ss[threadIdx.x*65 + j] = s;
        m = fmaxf(m, s);
    }
    float l = 0.f;
    float o[DIMH];
    #pragma unroll
    for (int d = 0; d < DIMH; d++) o[d] = 0.f;
    for (int j = 0; j < KVP; j++) {
        float p = expf(ss[threadIdx.x*65 + j] - m);
        l += p;
        #pragma unroll
        for (int d = 0; d < DIMH; d++) o[d] += p*vs[j*64 + d];
    }
    float inv = 1.f / l;
    #pragma unroll
    for (int d = 0; d < DIMH; d++) outp[(bg*CG + d)*NPIX + i] = o[d]*inv;
}

// ---------------- tiled SGEMM, FFMA2 over column pairs ----------------
// C = act(A[M,K] @ (B*s+t)[K,N] + bias[M]) (+resid)
__global__ void __launch_bounds__(256, 1)
sgemm_kernel(const float* __restrict__ A, const float* __restrict__ B,
             const float* __restrict__ bias, const float* __restrict__ scaleB,
             const float* __restrict__ shiftB, const float* __restrict__ resid,
             float* __restrict__ C, int M, int N, int K, int act) {
    __shared__ float As[16][132];
    __shared__ float Bs[16][132];
    int tid = threadIdx.x;
    int n0 = blockIdx.x*128, m0 = blockIdx.y*128;
    int zB = blockIdx.z * K * N;
    int zC = blockIdx.z * M * N;
    int ty = tid >> 4, tx = tid & 15;
    int aRow = tid >> 1, aCol = (tid & 1)*8;
    u64 acc[8][4];
    #pragma unroll
    for (int r = 0; r < 8; r++)
        #pragma unroll
        for (int c = 0; c < 4; c++) acc[r][c] = 0ull;

    for (int k0 = 0; k0 < K; k0 += 16) {
        #pragma unroll
        for (int c2 = 0; c2 < 8; c2++)
            As[aCol + c2][aRow] = A[(m0 + aRow)*K + k0 + aCol + c2];
        #pragma unroll
        for (int it = 0; it < 8; it++) {
            int idx = tid + it*256;
            int row = idx >> 7, col = idx & 127;
            float sc = scaleB ? scaleB[k0 + row] : 1.f;
            float sh = scaleB ? shiftB[k0 + row] : 0.f;
            Bs[row][col] = B[zB + (k0 + row)*N + n0 + col]*sc + sh;
        }
        __syncthreads();
        #pragma unroll
        for (int kk = 0; kk < 16; kk++) {
            u64 ap[8], bp[4];
            #pragma unroll
            for (int r = 0; r < 8; r++) { float a = As[kk][ty*8 + r]; ap[r] = pack2(a, a); }
            #pragma unroll
            for (int cp = 0; cp < 4; cp++)
                bp[cp] = pack2(Bs[kk][tx + 32*cp], Bs[kk][tx + 16 + 32*cp]);
            #pragma unroll
            for (int r = 0; r < 8; r++)
                #pragma unroll
                for (int cp = 0; cp < 4; cp++) ffma2(acc[r][cp], ap[r], bp[cp]);
        }
        __syncthreads();
    }
    #pragma unroll
    for (int r = 0; r < 8; r++) {
        int m = m0 + ty*8 + r;
        float bm = bias[m];
        #pragma unroll
        for (int cp = 0; cp < 4; cp++) {
            float lo, hi; unpack2(acc[r][cp], lo, hi);
            int nlo = n0 + tx + 32*cp;
            int nhi = nlo + 16;
            float vlo = lo + bm, vhi = hi + bm;
            if (act == 1) {
                vlo = 0.5f*vlo*(1.f + erff(vlo*0.70710678118654752f));
                vhi = 0.5f*vhi*(1.f + erff(vhi*0.70710678118654752f));
            }
            if (resid) { vlo += resid[zC + m*N + nlo]; vhi += resid[zC + m*N + nhi]; }
            C[zC + m*N + nlo] = vlo;
            C[zC + m*N + nhi] = vhi;
        }
    }
}

// ---------------- launch ----------------
extern "C" void kernel_launch(void* const* d_in, const int* in_sizes, int n_in,
                              void* d_out, int out_size) {
    const float* x        = (const float*)d_in[0];
    const float* n1_g     = (const float*)d_in[1];
    const float* n1_b     = (const float*)d_in[2];
    const float* n2_g     = (const float*)d_in[3];
    const float* n2_b     = (const float*)d_in[4];
    const float* q_w      = (const float*)d_in[5];
    const float* k_w      = (const float*)d_in[6];
    const float* v_w      = (const float*)d_in[7];
    const float* off_dw_w = (const float*)d_in[8];
    const float* off_dw_b = (const float*)d_in[9];
    const float* off_pw_w = (const float*)d_in[10];
    const float* cpb_w0   = (const float*)d_in[11];
    const float* cpb_b0   = (const float*)d_in[12];
    const float* cpb_w1   = (const float*)d_in[13];
    const float* cpb_b1   = (const float*)d_in[14];
    const float* cpb_w2   = (const float*)d_in[15];
    const float* cpb_b2   = (const float*)d_in[16];
    const float* out_w    = (const float*)d_in[17];
    const float* out_b    = (const float*)d_in[18];
    const float* mlp_w1   = (const float*)d_in[19];
    const float* mlp_b1   = (const float*)d_in[20];
    const float* mlp_w2   = (const float*)d_in[21];
    const float* mlp_b2   = (const float*)d_in[22];
    float* out = (float*)d_out;

    float *p_s1, *p_t1, *p_s2, *p_t2, *p_x1, *p_q, *p_op, *p_vg, *p_kv, *p_k, *p_v, *p_bias, *p_attn, *p_x2, *p_h;
    cudaGetSymbolAddress((void**)&p_s1, g_s1);
    cudaGetSymbolAddress((void**)&p_t1, g_t1);
    cudaGetSymbolAddress((void**)&p_s2, g_s2);
    cudaGetSymbolAddress((void**)&p_t2, g_t2);
    cudaGetSymbolAddress((void**)&p_x1, g_x1);
    cudaGetSymbolAddress((void**)&p_q,  g_q);
    cudaGetSymbolAddress((void**)&p_op, g_offpart);
    cudaGetSymbolAddress((void**)&p_vg, g_vgrid);
    cudaGetSymbolAddress((void**)&p_kv, g_kv);
    cudaGetSymbolAddress((void**)&p_k,  g_k);
    cudaGetSymbolAddress((void**)&p_v,  g_v);
    cudaGetSymbolAddress((void**)&p_bias, g_bias);
    cudaGetSymbolAddress((void**)&p_attn, g_attn);
    cudaGetSymbolAddress((void**)&p_x2, g_x2);
    cudaGetSymbolAddress((void**)&p_h,  g_h);

    cudaFuncSetAttribute(bias_kernel, cudaFuncAttributeMaxDynamicSharedMemorySize,
                         BIAS_SMEM_FLOATS*4);
    cudaFuncSetAttribute(attn_kernel, cudaFuncAttributeMaxDynamicSharedMemorySize,
                         ATT_SMEM_FLOATS*4);

    // 1) bn1
    bn_stats<<<CCH, 256>>>(x, n1_g, n1_b, p_s1, p_t1);
    bn_apply<<<BATCH*CCH*NPIX/256, 256>>>(x, p_s1, p_t1, p_x1);
    // 2) q = grouped conv
    gconv<<<dim3(NBG, 4), 256>>>(p_x1, q_w, p_q, NPIX);
    // 3) offsets -> normalized sample grid (two stages for parallelism)
    offsets_part<<<dim3(NBG, 16), 64>>>(p_q, off_dw_w, off_dw_b, off_pw_w, p_op);
    offsets_finish<<<NBG, 64>>>(p_op, p_vg);
    // 4) bilinear sample
    gridsample_kernel<<<NBG, 256>>>(p_x1, p_vg, p_kv);
    // 5) k, v grouped convs
    gconv<<<dim3(NBG, 1), 64>>>(p_kv, k_w, p_k, KVP);
    gconv<<<dim3(NBG, 1), 64>>>(p_kv, v_w, p_v, KVP);
    // 6) CPB bias MLP
    bias_kernel<<<NBG*512, 512, BIAS_SMEM_FLOATS*4>>>(p_vg, cpb_w0, cpb_b0, cpb_w1, cpb_b1,
                                                      cpb_w2, cpb_b2, p_bias);
    // 7) attention
    attn_kernel<<<dim3(NBG, NPIX/ATT_QT), ATT_QT, ATT_SMEM_FLOATS*4>>>(p_q, p_k, p_v, p_bias, p_attn);
    // 8) out projection + residual (x2 = x + W_out @ attn + b)
    sgemm_kernel<<<dim3(8, 4, BATCH), 256>>>(out_w, p_attn, out_b, nullptr, nullptr, x, p_x2,
                                             512, 1024, 512, 0);
    // 9) bn2 + FFN
    bn_stats<<<CCH, 256>>>(p_x2, n2_g, n2_b, p_s2, p_t2);
    sgemm_kernel<<<dim3(8, 16, BATCH), 256>>>(mlp_w1, p_x2, mlp_b1, p_s2, p_t2, nullptr, p_h,
                                              2048, 1024, 512, 1);
    sgemm_kernel<<<dim3(8, 4, BATCH), 256>>>(mlp_w2, p_h, mlp_b2, nullptr, nullptr, p_x2, out,
                                             512, 1024, 2048, 0);
}

// round 13
// speedup vs baseline: 3.9563x; 3.5173x over previous
#include <cuda_runtime.h>
#include <cuda_bf16.h>
#include <math.h>

// ---------------- problem constants ----------------
#define BATCH 2
#define CCH   512
#define NPIX  1024     // 32*32
#define GR    8
#define CG    64
#define NBG   16       // BATCH*GR
#define KVP   64       // 8*8
#define DIMH  64
#define SCALE 0.125f
#define EPSBN 1e-5f

// ---------------- bf16x2 / mma helpers ----------------
__device__ __forceinline__ unsigned pack_bf16(float lo, float hi) {
    unsigned r;
    asm("cvt.rn.bf16x2.f32 %0, %1, %2;" : "=r"(r) : "f"(hi), "f"(lo));
    return r;
}
__device__ __forceinline__ void mma_bf16(float& c0, float& c1, float& c2, float& c3,
                                         unsigned a0, unsigned a1, unsigned a2, unsigned a3,
                                         unsigned b0, unsigned b1) {
    asm volatile("mma.sync.aligned.m16n8k16.row.col.f32.bf16.bf16.f32 "
        "{%0,%1,%2,%3}, {%4,%5,%6,%7}, {%8,%9}, {%0,%1,%2,%3};"
        : "+f"(c0), "+f"(c1), "+f"(c2), "+f"(c3)
        : "r"(a0), "r"(a1), "r"(a2), "r"(a3), "r"(b0), "r"(b1));
}

// ---------------- device scratch (no allocation allowed) ----------------
__device__ float g_s1[CCH], g_t1[CCH], g_s2[CCH], g_t2[CCH];
__device__ float g_x1[BATCH*CCH*NPIX];      // bn1(x)
__device__ float g_q [BATCH*CCH*NPIX];      // grouped conv q (unscaled)
__device__ float g_offpart[NBG*16*KVP*2];   // offset partials
__device__ float g_vgrid[NBG*KVP*2];        // normalized sample grid (vx,vy)
__device__ float g_kv[NBG*CG*KVP];          // sampled features
__device__ float g_k [NBG*CG*KVP];
__device__ float g_v [NBG*CG*KVP];
__device__ float g_bias[NBG*NPIX*KVP];      // CPB bias
__device__ float g_attn[BATCH*CCH*NPIX];    // attention output
__device__ float g_x2[BATCH*CCH*NPIX];      // x + out-proj
__device__ float g_h [BATCH*4*CCH*NPIX];    // FFN hidden

// ---------------- batchnorm stats ----------------
__global__ void bn_stats(const float* __restrict__ x, const float* __restrict__ g,
                         const float* __restrict__ b, float* __restrict__ s, float* __restrict__ t) {
    int c = blockIdx.x;
    float sum = 0.f, sq = 0.f;
    for (int e = threadIdx.x; e < BATCH*NPIX; e += 256) {
        int bb = e >> 10, p = e & 1023;
        float v = x[(bb*CCH + c)*NPIX + p];
        sum += v; sq += v*v;
    }
    __shared__ float rs[256], rq[256];
    rs[threadIdx.x] = sum; rq[threadIdx.x] = sq;
    __syncthreads();
    for (int st = 128; st > 0; st >>= 1) {
        if (threadIdx.x < st) { rs[threadIdx.x] += rs[threadIdx.x+st]; rq[threadIdx.x] += rq[threadIdx.x+st]; }
        __syncthreads();
    }
    if (threadIdx.x == 0) {
        float m   = rs[0] / (float)(BATCH*NPIX);
        float var = rq[0] / (float)(BATCH*NPIX) - m*m;
        float sc  = g[c] * rsqrtf(var + EPSBN);
        s[c] = sc;
        t[c] = b[c] - m*sc;
    }
}

__global__ void bn_apply(const float* __restrict__ x, const float* __restrict__ s,
                         const float* __restrict__ t, float* __restrict__ y) {
    int i = blockIdx.x*256 + threadIdx.x;
    int c = (i >> 10) & (CCH-1);
    y[i] = x[i]*s[c] + t[c];
}

// ---------------- grouped 1x1 conv ----------------
__global__ void gconv(const float* __restrict__ in, const float* __restrict__ w,
                      float* __restrict__ out, int npix) {
    int bg = blockIdx.x;
    int g  = bg & (GR-1);
    int pix = blockIdx.y*blockDim.x + threadIdx.x;
    __shared__ float ws[CG*CG];
    for (int e = threadIdx.x; e < CG*CG; e += blockDim.x) ws[e] = w[g*CG*CG + e];
    __syncthreads();
    if (pix >= npix) return;
    float xr[CG];
    #pragma unroll
    for (int ci = 0; ci < CG; ci++) xr[ci] = in[(bg*CG + ci)*npix + pix];
    #pragma unroll 4
    for (int o = 0; o < CG; o++) {
        float acc = 0.f;
        #pragma unroll
        for (int ci = 0; ci < CG; ci++) acc += ws[o*CG + ci] * xr[ci];
        out[(bg*CG + o)*npix + pix] = acc;
    }
}

// ---------------- offsets, stage 1: per-channel-group partial sums ----------------
__global__ void offsets_part(const float* __restrict__ q, const float* __restrict__ dww,
                             const float* __restrict__ dwb, const float* __restrict__ pww,
                             float* __restrict__ part) {
    int bg = blockIdx.x, grp = blockIdx.y;
    int tid = threadIdx.x;               // 64 threads, one per 8x8 output pos
    int oy = tid >> 3, ox = tid & 7;
    float acc0 = 0.f, acc1 = 0.f;
    #pragma unroll
    for (int cc = 0; cc < 4; cc++) {
        int c = grp*4 + cc;
        const float* wc = dww + c*36;
        const float* qc = q + (bg*CG + c)*NPIX;
        float s = 0.f;
        #pragma unroll
        for (int ky = 0; ky < 6; ky++) {
            int iy = oy*4 - 1 + ky;
            if (iy < 0 || iy >= 32) continue;
            #pragma unroll
            for (int kx = 0; kx < 6; kx++) {
                int ix = ox*4 - 1 + kx;
                if (ix < 0 || ix >= 32) continue;
                s += wc[ky*6 + kx] * qc[iy*32 + ix];
            }
        }
        s += dwb[c];
        float ge = 0.5f*s*(1.f + erff(s*0.70710678118654752f));  // exact gelu
        acc0 += pww[c]      * ge;
        acc1 += pww[CG + c] * ge;
    }
    part[((bg*16 + grp)*KVP + tid)*2 + 0] = acc0;
    part[((bg*16 + grp)*KVP + tid)*2 + 1] = acc1;
}

// ---------------- offsets, stage 2: reduce + tanh + grid normalize ----------------
__global__ void offsets_finish(const float* __restrict__ part, float* __restrict__ vgrid) {
    int bg = blockIdx.x;
    int tid = threadIdx.x;               // 64
    int oy = tid >> 3, ox = tid & 7;
    float a0 = 0.f, a1 = 0.f;
    #pragma unroll
    for (int g = 0; g < 16; g++) {
        a0 += part[((bg*16 + g)*KVP + tid)*2 + 0];
        a1 += part[((bg*16 + g)*KVP + tid)*2 + 1];
    }
    float offx = tanhf(a0)*4.f;
    float offy = tanhf(a1)*4.f;
    float vx = 2.f*((float)ox + offx)/7.f - 1.f;
    float vy = 2.f*((float)oy + offy)/7.f - 1.f;
    vgrid[bg*(KVP*2) + tid*2 + 0] = vx;
    vgrid[bg*(KVP*2) + tid*2 + 1] = vy;
}

// ---------------- bilinear grid sample (zero padding) ----------------
__global__ void gridsample_kernel(const float* __restrict__ x1, const float* __restrict__ vgrid,
                                  float* __restrict__ kv) {
    int bg = blockIdx.x;
    for (int e = threadIdx.x; e < CG*KVP; e += blockDim.x) {
        int c = e >> 6, pos = e & 63;
        float vx = vgrid[bg*(KVP*2) + pos*2 + 0];
        float vy = vgrid[bg*(KVP*2) + pos*2 + 1];
        float xf = ((vx + 1.f)*32.f - 1.f)*0.5f;
        float yf = ((vy + 1.f)*32.f - 1.f)*0.5f;
        float x0 = floorf(xf), y0 = floorf(yf);
        float wx = xf - x0, wy = yf - y0;
        int x0i = (int)x0, y0i = (int)y0;
        const float* img = x1 + (bg*CG + c)*NPIX;
        float v00 = 0.f, v10 = 0.f, v01 = 0.f, v11 = 0.f;
        bool xa = (x0i   >= 0 && x0i   < 32), xb = (x0i+1 >= 0 && x0i+1 < 32);
        bool ya = (y0i   >= 0 && y0i   < 32), yb = (y0i+1 >= 0 && y0i+1 < 32);
        if (xa && ya) v00 = img[y0i*32 + x0i];
        if (xb && ya) v10 = img[y0i*32 + x0i+1];
        if (xa && yb) v01 = img[(y0i+1)*32 + x0i];
        if (xb && yb) v11 = img[(y0i+1)*32 + x0i+1];
        float v = v00*(1.f-wx)*(1.f-wy) + v10*wx*(1.f-wy) + v01*(1.f-wx)*wy + v11*wx*wy;
        kv[(bg*CG + c)*KVP + pos] = v;
    }
}

// ---------------- CPB bias MLP with bf16 tensor cores ----------------
// 2048 blocks x 256 threads. Block owns (bg, 8 i values) = 512 points, in 4 passes of 128.
// Per pass: build h1 (bf16 pairs in smem), then 8 warps do a 128x128x128 mma GEMM,
// epilogue relu + dot(w2) reduced via shfl within 4-lane groups.
#define BIAS_SMEM_BYTES ((128*68*2 + 256 + 128 + 128 + 128)*4)
__global__ void __launch_bounds__(256, 1)
bias_kernel(const float* __restrict__ vgrid,
            const float* __restrict__ w0, const float* __restrict__ b0,
            const float* __restrict__ w1, const float* __restrict__ b1,
            const float* __restrict__ w2, const float* __restrict__ b2,
            float* __restrict__ bias_out) {
    extern __shared__ unsigned smu[];
    unsigned* w1tb = smu;                 // [col][kp] stride 68
    unsigned* h1b  = smu + 128*68;        // [p][kp]   stride 68
    float* fsm = (float*)(smu + 2*128*68);
    float* w0s = fsm;                     // 256
    float* b0s = fsm + 256;               // 128
    float* b1s = fsm + 384;               // 128
    float* w2s = fsm + 512;               // 128

    int tid = threadIdx.x;
    int bg  = blockIdx.x >> 7;
    int i0  = (blockIdx.x & 127) << 3;
    int w   = tid >> 5, lane = tid & 31;
    int g   = lane >> 2, t4 = lane & 3;

    // load w1 transposed as bf16 pairs: w1tb[col][kp] = {w1[2kp][col], w1[2kp+1][col]}
    for (int e = tid; e < 128*64; e += 256) {
        int col = e & 127, kp = e >> 7;
        float lo = w1[(2*kp)*128 + col];
        float hi = w1[(2*kp+1)*128 + col];
        w1tb[col*68 + kp] = pack_bf16(lo, hi);
    }
    w0s[tid] = w0[tid];
    if (tid < 128) { b0s[tid] = b0[tid]; b1s[tid] = b1[tid]; w2s[tid] = w2[tid]; }
    float b2v = b2[0];

    // per-thread fixed point (for h1 build): p = tid>>1, two threads split kp range
    int p_h = tid >> 1;
    int half = (tid & 1) * 32;
    int j_h = p_h & 63;
    float vx_t = vgrid[bg*(KVP*2) + j_h*2 + 0];
    float vy_t = vgrid[bg*(KVP*2) + j_h*2 + 1];

    __syncthreads();

    for (int pass = 0; pass < 4; pass++) {
        if (pass) __syncthreads();   // previous mma reads of h1b complete
        // ---- build h1 for 128 points ----
        {
            int i = i0 + pass*2 + (p_h >> 6);
            float qx = 2.f*(float)(i & 31)/31.f - 1.f;
            float qy = 2.f*(float)(i >> 5)/31.f - 1.f;
            float px = qx - vx_t;
            float py = qy - vy_t;
            float f0 = copysignf(log1pf(fabsf(px)), px);
            float f1 = copysignf(log1pf(fabsf(py)), py);
            #pragma unroll 8
            for (int kp = half; kp < half + 32; kp++) {
                int k0i = 2*kp;
                float hlo = f0*w0s[k0i]   + f1*w0s[128 + k0i]   + b0s[k0i];
                float hhi = f0*w0s[k0i+1] + f1*w0s[128 + k0i+1] + b0s[k0i+1];
                hlo = hlo > 0.f ? hlo : 0.f;
                hhi = hhi > 0.f ? hhi : 0.f;
                h1b[p_h*68 + kp] = pack_bf16(hlo, hhi);
            }
        }
        __syncthreads();

        // ---- 128x128x128 mma: warp w owns rows w*16 .. w*16+15 ----
        float acc[16][4];
        #pragma unroll
        for (int nt = 0; nt < 16; nt++)
            #pragma unroll
            for (int c = 0; c < 4; c++) acc[nt][c] = 0.f;

        #pragma unroll
        for (int ks = 0; ks < 8; ks++) {
            int abase = (w*16 + g)*68 + ks*8 + t4;
            unsigned a0 = h1b[abase];
            unsigned a1 = h1b[abase + 8*68];
            unsigned a2 = h1b[abase + 4];
            unsigned a3 = h1b[abase + 8*68 + 4];
            #pragma unroll
            for (int nt = 0; nt < 16; nt++) {
                int bbase = (nt*8 + g)*68 + ks*8 + t4;
                unsigned bb0 = w1tb[bbase];
                unsigned bb1 = w1tb[bbase + 4];
                mma_bf16(acc[nt][0], acc[nt][1], acc[nt][2], acc[nt][3],
                         a0, a1, a2, a3, bb0, bb1);
            }
        }

        // ---- epilogue: relu + dot w2, reduce over 4-lane groups ----
        float plo = 0.f, phi = 0.f;
        #pragma unroll
        for (int nt = 0; nt < 16; nt++) {
            int col = nt*8 + 2*t4;
            float bl0 = b1s[col], bl1 = b1s[col+1];
            float wl0 = w2s[col], wl1 = w2s[col+1];
            float h;
            h = acc[nt][0] + bl0; plo += (h > 0.f ? h : 0.f)*wl0;
            h = acc[nt][1] + bl1; plo += (h > 0.f ? h : 0.f)*wl1;
            h = acc[nt][2] + bl0; phi += (h > 0.f ? h : 0.f)*wl0;
            h = acc[nt][3] + bl1; phi += (h > 0.f ? h : 0.f)*wl1;
        }
        plo += __shfl_xor_sync(0xffffffffu, plo, 1);
        plo += __shfl_xor_sync(0xffffffffu, plo, 2);
        phi += __shfl_xor_sync(0xffffffffu, phi, 1);
        phi += __shfl_xor_sync(0xffffffffu, phi, 2);
        if (t4 == 0) {
            int plo_p = w*16 + g;
            int phi_p = plo_p + 8;
            int ilo = i0 + pass*2 + (plo_p >> 6);
            int ihi = i0 + pass*2 + (phi_p >> 6);
            bias_out[((bg << 10) + ilo)*KVP + (plo_p & 63)] = plo + b2v;
            bias_out[((bg << 10) + ihi)*KVP + (phi_p & 63)] = phi + b2v;
        }
    }
}

// ---------------- attention: sim + bias, softmax over 64 kv, @V ----------------
#define ATT_QT 128
#define ATT_SMEM_FLOATS (64*64 + 64*64 + ATT_QT*65)
__global__ void attn_kernel(const float* __restrict__ q, const float* __restrict__ karr,
                            const float* __restrict__ varr, const float* __restrict__ bias,
                            float* __restrict__ outp) {
    extern __shared__ float sm[];
    float* ks = sm;                 // [j][d]
    float* vs = sm + 64*64;         // [j][d]
    float* ss = sm + 2*64*64;       // [tid][65]
    int bg = blockIdx.x;
    int i  = blockIdx.y*ATT_QT + threadIdx.x;
    for (int e = threadIdx.x; e < CG*KVP; e += ATT_QT) {
        int d = e >> 6, j = e & 63;
        ks[j*64 + d] = karr[(bg*CG + d)*KVP + j];
        vs[j*64 + d] = varr[(bg*CG + d)*KVP + j];
    }
    __syncthreads();
    float qr[DIMH];
    #pragma unroll
    for (int d = 0; d < DIMH; d++) qr[d] = q[(bg*CG + d)*NPIX + i] * SCALE;
    const float* brow = bias + (bg*NPIX + i)*KVP;
    float m = -1e30f;
    for (int j = 0; j < KVP; j++) {
        float s = 0.f;
        #pragma unroll
        for (int d = 0; d < DIMH; d++) s += qr[d]*ks[j*64 + d];
        s += brow[j];
        ss[threadIdx.x*65 + j] = s;
        m = fmaxf(m, s);
    }
    float l = 0.f;
    float o[DIMH];
    #pragma unroll
    for (int d = 0; d < DIMH; d++) o[d] = 0.f;
    for (int j = 0; j < KVP; j++) {
        float p = expf(ss[threadIdx.x*65 + j] - m);
        l += p;
        #pragma unroll
        for (int d = 0; d < DIMH; d++) o[d] += p*vs[j*64 + d];
    }
    float inv = 1.f / l;
    #pragma unroll
    for (int d = 0; d < DIMH; d++) outp[(bg*CG + d)*NPIX + i] = o[d]*inv;
}

// ---------------- bf16 tensor-core SGEMM ----------------
// C = act(A[M,K] @ (B*s+t)[K,N] + bias[M]) (+resid). Block 128x128, 8 warps (2m x 4n), k-chunk 32.
__global__ void __launch_bounds__(256, 1)
sgemm_tc(const float* __restrict__ A, const float* __restrict__ B,
         const float* __restrict__ bias, const float* __restrict__ scaleB,
         const float* __restrict__ shiftB, const float* __restrict__ resid,
         float* __restrict__ C, int M, int N, int K, int act) {
    __shared__ unsigned Ab[128*20];   // [row][kp] stride 20 (16 data + 4 pad)
    __shared__ unsigned Bb[128*20];   // [col][kp] stride 20
    int tid = threadIdx.x;
    int n0 = blockIdx.x*128, m0 = blockIdx.y*128;
    int zB = blockIdx.z * K * N;
    int zC = blockIdx.z * M * N;
    int w = tid >> 5, lane = tid & 31;
    int g = lane >> 2, t4 = lane & 3;
    int wm = w & 1, wn = w >> 1;

    float acc[4][4][4];
    #pragma unroll
    for (int mt = 0; mt < 4; mt++)
        #pragma unroll
        for (int nt = 0; nt < 4; nt++)
            #pragma unroll
            for (int c = 0; c < 4; c++) acc[mt][nt][c] = 0.f;

    for (int k0 = 0; k0 < K; k0 += 32) {
        // load A tile: 128 rows x 32 k -> bf16 pairs
        #pragma unroll
        for (int s = 0; s < 8; s++) {
            int e = tid + s*256;
            int kp = e & 15, row = e >> 4;
            float2 v = *reinterpret_cast<const float2*>(&A[(m0 + row)*K + k0 + 2*kp]);
            Ab[row*20 + kp] = pack_bf16(v.x, v.y);
        }
        // load B tile: 32 k x 128 cols -> bf16 pairs over k, optional bn scale
        #pragma unroll
        for (int s = 0; s < 8; s++) {
            int e = tid + s*256;
            int col = e & 127, kp = e >> 7;
            int kk = k0 + 2*kp;
            float blo = B[zB + kk*N + n0 + col];
            float bhi = B[zB + (kk+1)*N + n0 + col];
            if (scaleB) {
                blo = blo*scaleB[kk]   + shiftB[kk];
                bhi = bhi*scaleB[kk+1] + shiftB[kk+1];
            }
            Bb[col*20 + kp] = pack_bf16(blo, bhi);
        }
        __syncthreads();

        #pragma unroll
        for (int kseg = 0; kseg < 2; kseg++) {
            unsigned afr[4][4], bfr[4][2];
            #pragma unroll
            for (int mt = 0; mt < 4; mt++) {
                int ab = (wm*64 + mt*16 + g)*20 + kseg*8 + t4;
                afr[mt][0] = Ab[ab];
                afr[mt][1] = Ab[ab + 8*20];
                afr[mt][2] = Ab[ab + 4];
                afr[mt][3] = Ab[ab + 8*20 + 4];
            }
            #pragma unroll
            for (int nt = 0; nt < 4; nt++) {
                int bb = (wn*32 + nt*8 + g)*20 + kseg*8 + t4;
                bfr[nt][0] = Bb[bb];
                bfr[nt][1] = Bb[bb + 4];
            }
            #pragma unroll
            for (int mt = 0; mt < 4; mt++)
                #pragma unroll
                for (int nt = 0; nt < 4; nt++)
                    mma_bf16(acc[mt][nt][0], acc[mt][nt][1], acc[mt][nt][2], acc[mt][nt][3],
                             afr[mt][0], afr[mt][1], afr[mt][2], afr[mt][3],
                             bfr[nt][0], bfr[nt][1]);
        }
        __syncthreads();
    }

    // epilogue
    #pragma unroll
    for (int mt = 0; mt < 4; mt++) {
        #pragma unroll
        for (int hf = 0; hf < 2; hf++) {
            int m = m0 + wm*64 + mt*16 + g + hf*8;
            float bm = bias[m];
            #pragma unroll
            for (int nt = 0; nt < 4; nt++) {
                int col = n0 + wn*32 + nt*8 + 2*t4;
                float v0 = acc[mt][nt][hf*2]     + bm;
                float v1 = acc[mt][nt][hf*2 + 1] + bm;
                if (act == 1) {
                    v0 = 0.5f*v0*(1.f + erff(v0*0.70710678118654752f));
                    v1 = 0.5f*v1*(1.f + erff(v1*0.70710678118654752f));
                }
                if (resid) {
                    float2 rv = *reinterpret_cast<const float2*>(&resid[zC + m*N + col]);
                    v0 += rv.x; v1 += rv.y;
                }
                float2 ov; ov.x = v0; ov.y = v1;
                *reinterpret_cast<float2*>(&C[zC + m*N + col]) = ov;
            }
        }
    }
}

// ---------------- launch ----------------
extern "C" void kernel_launch(void* const* d_in, const int* in_sizes, int n_in,
                              void* d_out, int out_size) {
    const float* x        = (const float*)d_in[0];
    const float* n1_g     = (const float*)d_in[1];
    const float* n1_b     = (const float*)d_in[2];
    const float* n2_g     = (const float*)d_in[3];
    const float* n2_b     = (const float*)d_in[4];
    const float* q_w      = (const float*)d_in[5];
    const float* k_w      = (const float*)d_in[6];
    const float* v_w      = (const float*)d_in[7];
    const float* off_dw_w = (const float*)d_in[8];
    const float* off_dw_b = (const float*)d_in[9];
    const float* off_pw_w = (const float*)d_in[10];
    const float* cpb_w0   = (const float*)d_in[11];
    const float* cpb_b0   = (const float*)d_in[12];
    const float* cpb_w1   = (const float*)d_in[13];
    const float* cpb_b1   = (const float*)d_in[14];
    const float* cpb_w2   = (const float*)d_in[15];
    const float* cpb_b2   = (const float*)d_in[16];
    const float* out_w    = (const float*)d_in[17];
    const float* out_b    = (const float*)d_in[18];
    const float* mlp_w1   = (const float*)d_in[19];
    const float* mlp_b1   = (const float*)d_in[20];
    const float* mlp_w2   = (const float*)d_in[21];
    const float* mlp_b2   = (const float*)d_in[22];
    float* out = (float*)d_out;

    float *p_s1, *p_t1, *p_s2, *p_t2, *p_x1, *p_q, *p_op, *p_vg, *p_kv, *p_k, *p_v, *p_bias, *p_attn, *p_x2, *p_h;
    cudaGetSymbolAddress((void**)&p_s1, g_s1);
    cudaGetSymbolAddress((void**)&p_t1, g_t1);
    cudaGetSymbolAddress((void**)&p_s2, g_s2);
    cudaGetSymbolAddress((void**)&p_t2, g_t2);
    cudaGetSymbolAddress((void**)&p_x1, g_x1);
    cudaGetSymbolAddress((void**)&p_q,  g_q);
    cudaGetSymbolAddress((void**)&p_op, g_offpart);
    cudaGetSymbolAddress((void**)&p_vg, g_vgrid);
    cudaGetSymbolAddress((void**)&p_kv, g_kv);
    cudaGetSymbolAddress((void**)&p_k,  g_k);
    cudaGetSymbolAddress((void**)&p_v,  g_v);
    cudaGetSymbolAddress((void**)&p_bias, g_bias);
    cudaGetSymbolAddress((void**)&p_attn, g_attn);
    cudaGetSymbolAddress((void**)&p_x2, g_x2);
    cudaGetSymbolAddress((void**)&p_h,  g_h);

    cudaFuncSetAttribute(bias_kernel, cudaFuncAttributeMaxDynamicSharedMemorySize,
                         BIAS_SMEM_BYTES);
    cudaFuncSetAttribute(attn_kernel, cudaFuncAttributeMaxDynamicSharedMemorySize,
                         ATT_SMEM_FLOATS*4);

    // 1) bn1
    bn_stats<<<CCH, 256>>>(x, n1_g, n1_b, p_s1, p_t1);
    bn_apply<<<BATCH*CCH*NPIX/256, 256>>>(x, p_s1, p_t1, p_x1);
    // 2) q = grouped conv
    gconv<<<dim3(NBG, 4), 256>>>(p_x1, q_w, p_q, NPIX);
    // 3) offsets -> normalized sample grid
    offsets_part<<<dim3(NBG, 16), 64>>>(p_q, off_dw_w, off_dw_b, off_pw_w, p_op);
    offsets_finish<<<NBG, 64>>>(p_op, p_vg);
    // 4) bilinear sample
    gridsample_kernel<<<NBG, 256>>>(p_x1, p_vg, p_kv);
    // 5) k, v grouped convs
    gconv<<<dim3(NBG, 1), 64>>>(p_kv, k_w, p_k, KVP);
    gconv<<<dim3(NBG, 1), 64>>>(p_kv, v_w, p_v, KVP);
    // 6) CPB bias MLP (tensor cores)
    bias_kernel<<<NBG*128, 256, BIAS_SMEM_BYTES>>>(p_vg, cpb_w0, cpb_b0, cpb_w1, cpb_b1,
                                                   cpb_w2, cpb_b2, p_bias);
    // 7) attention
    attn_kernel<<<dim3(NBG, NPIX/ATT_QT), ATT_QT, ATT_SMEM_FLOATS*4>>>(p_q, p_k, p_v, p_bias, p_attn);
    // 8) out projection + residual
    sgemm_tc<<<dim3(8, 4, BATCH), 256>>>(out_w, p_attn, out_b, nullptr, nullptr, x, p_x2,
                                         512, 1024, 512, 0);
    // 9) bn2 + FFN
    bn_stats<<<CCH, 256>>>(p_x2, n2_g, n2_b, p_s2, p_t2);
    sgemm_tc<<<dim3(8, 16, BATCH), 256>>>(mlp_w1, p_x2, mlp_b1, p_s2, p_t2, nullptr, p_h,
                                          2048, 1024, 512, 1);
    sgemm_tc<<<dim3(8, 4, BATCH), 256>>>(mlp_w2, p_h, mlp_b2, nullptr, nullptr, p_x2, out,
                                         512, 1024, 2048, 0);
}